// round 15
// baseline (speedup 1.0000x reference)
#include <cuda_runtime.h>
#include <cuda_fp16.h>

// Shapes fixed by the problem: B=16, P=12, N=2048, H=64, E=16384, Q=P.
#define BB 16
#define PP 12
#define NN 2048
#define HH 64
#define NH (NN*HH)          // 131072
#define BPc (BB*PP)         // 192
#define EE 16384
#define EPSV 1e-5f
#define BSTRIDE (NN*PP*HH*2)   // 3,145,728 bytes: one batch slice of g_xgh
#define CH1 16                  // stats1 partials per bp

// -------- scratch in __device__ globals (no allocations allowed) ----------
// g_xgh layout: [b][n][p][h] (fp16 x*gw) -> per-node row of 1536B contiguous
__device__ __half2 g_xgh[BB*NN*PP*HH/2];   // 50 MB
// g_yh layout: [b][p][n][h] (fp16 y)
__device__ __half2 g_yh [BB*PP*NN*HH/2];   // 50 MB
__device__ float2  g_part1[BPc*CH1];
__device__ float2  g_part2[BPc*256];
__device__ float2  g_stats2[BPc];
__device__ int     g_rowptr[NN+1];
__device__ uint2   g_sn[EE];            // per sorted slot: (src*64, norm bits)
__device__ uint2   g_AB[NN*32];         // packed half2 A | half2 B per (node, h-pair)

// ---------------- CSR build: ONE single-block kernel, smem-resident -------
#define SMEM_CSR (EE*4*3 + NN*4 + (NN+1)*4 + NN*4 + 128)
__global__ void k_csr(const void* __restrict__ ei) {
    extern __shared__ char sraw[];
    int*   sdst  = (int*)sraw;
    int*   ssrc  = sdst + EE;
    int*   sbuck = ssrc + EE;
    int*   sdeg  = sbuck + EE;        // doubles as scatter cursor later
    int*   srp   = sdeg + NN;
    float* sdinv = (float*)(srp + NN + 1);
    int*   swarp = (int*)(sdinv + NN);
    __shared__ int s_is64;
    int t = threadIdx.x, lane = t & 31, wid = t >> 5;

    // edge dtype detection (jax may emit int32 despite jnp.int64)
    if (t < 32) {
        long long v = ((const long long*)ei)[t];
        int ok = (v >= 0 && v < (long long)NN);
        unsigned m = __ballot_sync(0xffffffffu, ok);
        if (t == 0) s_is64 = (m == 0xffffffffu) ? 1 : 0;
    }
    for (int i = t; i < NN; i += 1024) sdeg[i] = 0;
    __syncthreads();
    int is64 = s_is64;

    for (int e = t; e < EE; e += 1024) {
        int s, d;
        if (is64) {
            s = (int)((const long long*)ei)[e];
            d = (int)((const long long*)ei)[EE + e];
        } else {
            s = ((const int*)ei)[e];
            d = ((const int*)ei)[EE + e];
        }
        ssrc[e] = s; sdst[e] = d;
        atomicAdd(&sdeg[d], 1);
    }
    __syncthreads();

    // exclusive scan of deg[2048] via warp shuffles
    int a  = sdeg[2*t], b2 = sdeg[2*t+1];
    int v  = a + b2;
    #pragma unroll
    for (int off = 1; off < 32; off <<= 1) {
        int u = __shfl_up_sync(0xffffffffu, v, off);
        if (lane >= off) v += u;
    }
    if (lane == 31) swarp[wid] = v;
    __syncthreads();
    if (wid == 0) {
        int u = swarp[lane];
        #pragma unroll
        for (int off = 1; off < 32; off <<= 1) {
            int x2 = __shfl_up_sync(0xffffffffu, u, off);
            if (lane >= off) u += x2;
        }
        swarp[lane] = u;
    }
    __syncthreads();
    int woff = wid ? swarp[wid-1] : 0;
    int incl = v + woff;
    int excl = incl - (a + b2);
    srp[2*t]   = excl;        g_rowptr[2*t]   = excl;
    srp[2*t+1] = excl + a;    g_rowptr[2*t+1] = excl + a;
    if (t == 1023) { srp[NN] = incl; g_rowptr[NN] = incl; }
    sdinv[2*t]   = a  ? rsqrtf((float)a)  : 0.f;
    sdinv[2*t+1] = b2 ? rsqrtf((float)b2) : 0.f;
    sdeg[2*t] = 0; sdeg[2*t+1] = 0;
    __syncthreads();

    for (int e = t; e < EE; e += 1024) {
        int d = sdst[e];
        int pos = srp[d] + atomicAdd(&sdeg[d], 1);
        sbuck[pos] = e;
    }
    __syncthreads();

    // sort each bucket by edge id (deterministic accumulation), fill (src*64, norm)
    for (int n = t; n < NN; n += 1024) {
        int beg = srp[n], end = srp[n+1];
        for (int i = beg + 1; i < end; i++) {
            int key = sbuck[i]; int j = i - 1;
            while (j >= beg && sbuck[j] > key) { sbuck[j+1] = sbuck[j]; j--; }
            sbuck[j+1] = key;
        }
        float dn = sdinv[n];
        for (int i = beg; i < end; i++) {
            int s = ssrc[sbuck[i]];
            g_sn[i] = make_uint2((unsigned)(s * HH),
                                 __float_as_uint(sdinv[s] * dn));
        }
    }
}

// ---- A[dst,h]=Σnrm*gw[src,h], B[dst,h]=Σnrm*gb[src,h] (bp-independent) ---
__global__ void k_ab(const float* __restrict__ gw, const float* __restrict__ gb) {
    int w = threadIdx.x >> 5, l = threadIdx.x & 31;
    int n = blockIdx.x * 8 + w;
    int beg = g_rowptr[n], end = g_rowptr[n+1];
    float A0 = 0.f, A1 = 0.f, B0 = 0.f, B1 = 0.f;
    for (int i = beg; i < end; i++) {
        uint2 sn = g_sn[i];                 // sn.x = src*64 (float offset)
        float nrm = __uint_as_float(sn.y);
        float2 w2 = *(const float2*)(gw + sn.x + 2*l);
        float2 b2 = *(const float2*)(gb + sn.x + 2*l);
        A0 = fmaf(nrm, w2.x, A0); A1 = fmaf(nrm, w2.y, A1);
        B0 = fmaf(nrm, b2.x, B0); B1 = fmaf(nrm, b2.y, B1);
    }
    __half2 hA = __floats2half2_rn(A0, A1);
    __half2 hB = __floats2half2_rn(B0, B1);
    g_AB[n*32 + l] = make_uint2(*reinterpret_cast<unsigned*>(&hA),
                                *reinterpret_cast<unsigned*>(&hB));
}

// -------- LN1 stats + fp16(x*gw) write in [b][n][p][h] layout -------------
// chunked over bp (bp = bp0 + blockIdx.y); CH1=16 partials per bp so each
// per-quad chunk still launches 16*48 = 768 blocks (full-grid parallelism).
__global__ void k_stats1(const float4* __restrict__ x4,
                         const float4* __restrict__ gw4, int bp0) {
    int bp = bp0 + blockIdx.y, ch = blockIdx.x, t = threadIdx.x;
    int b = bp / PP, p = bp - b*PP;
    float s = 0.f, q = 0.f;
    uint2* xg2 = (uint2*)g_xgh;
    #pragma unroll
    for (int i = 0; i < 8; i++) {
        int loc = ch*2048 + i*256 + t;            // float4 index within slice
        float4 v = x4[bp*(NH/4) + loc];
        s += v.x + v.y + v.z + v.w;
        q += v.x*v.x + v.y*v.y + v.z*v.z + v.w*v.w;
        float4 g = gw4[loc];
        __half2 h0 = __floats2half2_rn(v.x*g.x, v.y*g.y);
        __half2 h1 = __floats2half2_rn(v.z*g.z, v.w*g.w);
        int n  = loc >> 4;                        // node
        int h4 = loc & 15;                        // 4-half group within row
        xg2[((b*NN + n)*PP + p)*16 + h4] =
            make_uint2(*reinterpret_cast<unsigned*>(&h0),
                       *reinterpret_cast<unsigned*>(&h1));
    }
    __shared__ float ss[256], sq[256];
    ss[t] = s; sq[t] = q; __syncthreads();
    for (int off = 128; off > 0; off >>= 1) {
        if (t < off) { ss[t] += ss[t+off]; sq[t] += sq[t+off]; }
        __syncthreads();
    }
    if (t == 0) g_part1[bp*CH1 + ch] = make_float2(ss[0], sq[0]);
}

// -- fused gather: warp = (node, p-group of 4, batch-QUAD bq param) --------
__device__ __forceinline__ void upd(unsigned u, float nrm, float2& a) {
    float2 f = __half22float2(*reinterpret_cast<__half2*>(&u));
    a.x = fmaf(nrm, f.x, a.x);
    a.y = fmaf(nrm, f.y, a.y);
}
__device__ __forceinline__ void upd4(const uint4& c, float nrm, float2* a) {
    upd(c.x, nrm, a[0]); upd(c.y, nrm, a[1]);
    upd(c.z, nrm, a[2]); upd(c.w, nrm, a[3]);
}
__device__ __forceinline__ void loadrow(const char* base, unsigned off, uint4* dst) {
    const char* p = base + off * 24u;
    dst[0] = *(const uint4*)p;
    dst[1] = *(const uint4*)(p + BSTRIDE);
    dst[2] = *(const uint4*)(p + 2*BSTRIDE);
    dst[3] = *(const uint4*)(p + 3*(size_t)BSTRIDE);
}

__global__ void __launch_bounds__(256, 3) k_conv(int bq) {
    __shared__ float2 sstats[4][PP];
    __shared__ float  ssum[4][4][8], ssq[4][4][8];   // [bsel][pg][warp]
    int g  = blockIdx.y;                             // p-group: p = 4g..4g+3
    int t  = threadIdx.x;
    if (t < 4*PP) {                                  // inline LN1 finalize (4 b)
        int bsel = t / PP, p = t - bsel*PP;
        int bp = (4*bq + bsel)*PP + p;
        float s = 0.f, q = 0.f;
        #pragma unroll
        for (int i = 0; i < CH1; i++) {
            float2 v = g_part1[bp*CH1+i]; s += v.x; q += v.y;
        }
        float mean = s / (float)NH;
        float var  = q / (float)NH - mean*mean;
        sstats[bsel][p] = make_float2(mean, rsqrtf(var + EPSV));
    }
    __syncthreads();

    int w = t >> 5, l = t & 31;
    int n = blockIdx.x * 8 + w;
    int beg = g_rowptr[n], end = g_rowptr[n+1];
    // lane base for b0; b1..b3 = +BSTRIDE..+3*BSTRIDE (mostly LDG imm offsets)
    const char* base = (const char*)g_xgh
                     + (size_t)(4*bq) * BSTRIDE + (g*32 + l) * 16;

    float2 acc[4][4];                                 // [bsel][m]
    #pragma unroll
    for (int bs = 0; bs < 4; bs++)
        #pragma unroll
        for (int m = 0; m < 4; m++) acc[bs][m] = make_float2(0.f, 0.f);

    int len = end - beg;
    const uint2* sp = g_sn + beg;
    uint2 iA, iB;
    uint4 vA[4], vB[4];
    if (len > 0) { iA = sp[0]; loadrow(base, iA.x, vA); }
    if (len > 1) { iB = sp[1]; loadrow(base, iB.x, vB); }
    int j = 0;
    for (; j + 2 < len; j += 2) {
        float nA = __uint_as_float(iA.y);
        #pragma unroll
        for (int bs = 0; bs < 4; bs++) upd4(vA[bs], nA, acc[bs]);
        iA = sp[j+2];                                  // slot A refills itself
        loadrow(base, iA.x, vA);
        float nB = __uint_as_float(iB.y);
        #pragma unroll
        for (int bs = 0; bs < 4; bs++) upd4(vB[bs], nB, acc[bs]);
        if (j + 3 < len) {                             // slot B refills itself
            iB = sp[j+3];
            loadrow(base, iB.x, vB);
        }
    }
    if (j < len) {
        float nA = __uint_as_float(iA.y);
        #pragma unroll
        for (int bs = 0; bs < 4; bs++) upd4(vA[bs], nA, acc[bs]);
    }
    if (j + 1 < len) {
        float nB = __uint_as_float(iB.y);
        #pragma unroll
        for (int bs = 0; bs < 4; bs++) upd4(vB[bs], nB, acc[bs]);
    }

    // lane l owns p = 4g + (l>>3), h = 8*(l&7)..+7
    int g8 = l & 7, pg = l >> 3;
    int p  = 4*g + pg;
    uint2 ab[4];
    #pragma unroll
    for (int m = 0; m < 4; m++) ab[m] = g_AB[n*32 + 4*g8 + m];

    #pragma unroll
    for (int bsel = 0; bsel < 4; bsel++) {
        float2 st = sstats[bsel][p];
        float r = st.y, mr = st.x * st.y;
        unsigned hy[4];
        float s1 = 0.f, q1 = 0.f;
        #pragma unroll
        for (int m = 0; m < 4; m++) {
            float2 A  = __half22float2(*reinterpret_cast<__half2*>(&ab[m].x));
            float2 Bv = __half22float2(*reinterpret_cast<__half2*>(&ab[m].y));
            float y0 = fmaf(r, acc[bsel][m].x, fmaf(-mr, A.x, Bv.x));
            float y1 = fmaf(r, acc[bsel][m].y, fmaf(-mr, A.y, Bv.y));
            __half2 h = __floats2half2_rn(y0, y1);
            hy[m] = *reinterpret_cast<unsigned*>(&h);
            s1 += y0 + y1;
            q1 += y0*y0 + y1*y1;
        }
        ((uint4*)g_yh)[(size_t)((4*bq + bsel)*PP + p)*(NH/8) + n*8 + g8] =
            make_uint4(hy[0], hy[1], hy[2], hy[3]);
        // deterministic butterfly over the 8 lanes sharing this p
        #pragma unroll
        for (int off = 1; off < 8; off <<= 1) {
            s1 += __shfl_xor_sync(0xffffffffu, s1, off);
            q1 += __shfl_xor_sync(0xffffffffu, q1, off);
        }
        if (g8 == 0) { ssum[bsel][pg][w] = s1; ssq[bsel][pg][w] = q1; }
    }
    __syncthreads();
    if (t < 16) {
        int bsel = t >> 2, pq = t & 3;
        float s = 0.f, q = 0.f;
        for (int i = 0; i < 8; i++) { s += ssum[bsel][pq][i]; q += ssq[bsel][pq][i]; }
        g_part2[((4*bq + bsel)*PP + 4*g + pq)*256 + blockIdx.x] = make_float2(s, q);
    }
}

// chunked over bp: bp = bp0 + blockIdx.x
__global__ void k_stats2(int bp0) {
    int bp = bp0 + blockIdx.x, t = threadIdx.x;
    float2 v = g_part2[bp*256 + t];
    __shared__ float ss[256], sq[256];
    ss[t] = v.x; sq[t] = v.y; __syncthreads();
    for (int off = 128; off > 0; off >>= 1) {
        if (t < off) { ss[t] += ss[t+off]; sq[t] += sq[t+off]; }
        __syncthreads();
    }
    if (t == 0) {
        float mean = ss[0] / (float)NH;
        float var  = sq[0] / (float)NH - mean*mean;
        g_stats2[bp] = make_float2(mean, rsqrtf(var + EPSV));
    }
}

// -------- fused LN2 + 1x1 conv over periods + bias (float4 vectorized) ----
// chunked over blocks: gid covers batches [blk0*256>>15 ...)
__global__ void k_out(const float4* __restrict__ tw4,
                      const float4* __restrict__ tb4,
                      const float*  __restrict__ cw,
                      const float*  __restrict__ cb,
                      float4* __restrict__ out4, int blk0) {
    __shared__ float  scw[144], srow[12], scb[12];
    __shared__ float2 sst[12];
    int t   = threadIdx.x;
    int gid = (blk0 + blockIdx.x) * 256 + t;  // 524288 total (16 b * 2048 n * 16 h4)
    int b   = gid >> 15;                      // 32768 positions per batch
    if (t < 144)             scw[t]       = cw[t];
    if (t >= 144 && t < 156) scb[t-144]   = cb[t-144];
    if (t >= 160 && t < 172) sst[t-160]   = g_stats2[b*PP + (t-160)];
    __syncthreads();
    if (t < 12) {
        float s = 0.f;
        for (int p = 0; p < 12; p++) s += scw[t*12 + p];
        srow[t] = s;
    }
    __syncthreads();

    int h4   = gid & 15;
    int n    = (gid >> 4) & 2047;
    int pos4 = n*16 + h4;

    const uint2* y4 = (const uint2*)g_yh;
    float4 tv[12];
    #pragma unroll
    for (int p = 0; p < 12; p++) {
        uint2 u = y4[(b*PP + p)*(NH/4) + pos4];
        float2 f0 = __half22float2(*reinterpret_cast<__half2*>(&u.x));
        float2 f1 = __half22float2(*reinterpret_cast<__half2*>(&u.y));
        float2 st = sst[p];
        tv[p].x = (f0.x - st.x) * st.y;
        tv[p].y = (f0.y - st.x) * st.y;
        tv[p].z = (f1.x - st.x) * st.y;
        tv[p].w = (f1.y - st.x) * st.y;
    }
    float4 tw = tw4[pos4];
    float4 tb = tb4[pos4];

    #pragma unroll
    for (int q = 0; q < 12; q++) {
        float ax = 0.f, ay = 0.f, az = 0.f, aw = 0.f;
        #pragma unroll
        for (int p = 0; p < 12; p++) {
            float c = scw[q*12 + p];
            ax = fmaf(c, tv[p].x, ax);
            ay = fmaf(c, tv[p].y, ay);
            az = fmaf(c, tv[p].z, az);
            aw = fmaf(c, tv[p].w, aw);
        }
        float4 o;
        o.x = fmaf(tw.x, ax, fmaf(tb.x, srow[q], scb[q]));
        o.y = fmaf(tw.y, ay, fmaf(tb.y, srow[q], scb[q]));
        o.z = fmaf(tw.z, az, fmaf(tb.z, srow[q], scb[q]));
        o.w = fmaf(tw.w, aw, fmaf(tb.w, srow[q], scb[q]));
        out4[(b*PP + q)*(NH/4) + pos4] = o;
    }
}

// ---- one-time host objects (created at load, before harness checkpoints) --
struct _CondBlockInit {
    cudaStream_t sB, sC, sO;
    cudaEvent_t  evFork, evJoin, evS1[4], evCv[4], evOut;
    _CondBlockInit() {
        cudaStreamCreateWithFlags(&sB, cudaStreamNonBlocking);
        cudaStreamCreateWithFlags(&sC, cudaStreamNonBlocking);
        cudaStreamCreateWithFlags(&sO, cudaStreamNonBlocking);
        cudaEventCreateWithFlags(&evFork, cudaEventDisableTiming);
        cudaEventCreateWithFlags(&evJoin, cudaEventDisableTiming);
        for (int q = 0; q < 4; q++) {
            cudaEventCreateWithFlags(&evS1[q], cudaEventDisableTiming);
            cudaEventCreateWithFlags(&evCv[q], cudaEventDisableTiming);
        }
        cudaEventCreateWithFlags(&evOut, cudaEventDisableTiming);
        cudaFuncSetAttribute(k_csr, cudaFuncAttributeMaxDynamicSharedMemorySize,
                             SMEM_CSR);
    }
};
static _CondBlockInit g_ini;

// --------------------------------------------------------------------------
extern "C" void kernel_launch(void* const* d_in, const int* in_sizes, int n_in,
                              void* d_out, int out_size) {
    const float* x  = (const float*)d_in[0];
    const void*  ei = d_in[1];
    const float* gw = (const float*)d_in[2];
    const float* gb = (const float*)d_in[3];
    const float* tw = (const float*)d_in[4];
    const float* tb = (const float*)d_in[5];
    const float* cw = (const float*)d_in[6];
    const float* cb = (const float*)d_in[7];
    float4* out = (float4*)d_out;

    // fork: side stream sB runs CSR build + AB precompute.
    cudaEventRecord(g_ini.evFork, 0);
    cudaStreamWaitEvent(g_ini.sB, g_ini.evFork, 0);
    k_csr <<<1, 1024, SMEM_CSR, g_ini.sB>>>(ei);
    k_ab  <<<256, 256, 0, g_ini.sB>>>(gw, gb);
    cudaEventRecord(g_ini.evJoin, g_ini.sB);

    // stage 1: stats1 in 4 batch-quad chunks, each with FULL grid parallelism
    for (int q = 0; q < 4; q++) {
        k_stats1 <<<dim3(CH1, 48), 256>>>((const float4*)x, (const float4*)gw, q*48);
        cudaEventRecord(g_ini.evS1[q], 0);
    }

    // stage 2: conv + stats2 per quad on stream sC (waits csr/ab + its chunk)
    cudaStreamWaitEvent(g_ini.sC, g_ini.evJoin, 0);
    for (int q = 0; q < 4; q++) {
        cudaStreamWaitEvent(g_ini.sC, g_ini.evS1[q], 0);
        k_conv   <<<dim3(NN/8, 3, 1), 256, 0, g_ini.sC>>>(q);
        k_stats2 <<<48, 256, 0, g_ini.sC>>>(q*48);
        cudaEventRecord(g_ini.evCv[q], g_ini.sC);
    }

    // stage 3: out per quad on stream sO
    for (int q = 0; q < 4; q++) {
        cudaStreamWaitEvent(g_ini.sO, g_ini.evCv[q], 0);
        k_out <<<512, 256, 0, g_ini.sO>>>((const float4*)tw, (const float4*)tb,
                                          cw, cb, out, q*512);
    }
    cudaEventRecord(g_ini.evOut, g_ini.sO);

    // join everything back to the main (capture) stream
    cudaStreamWaitEvent(0, g_ini.evOut, 0);
}

// round 16
// speedup vs baseline: 1.0381x; 1.0381x over previous
#include <cuda_runtime.h>
#include <cuda_fp16.h>

// Shapes fixed by the problem: B=16, P=12, N=2048, H=64, E=16384, Q=P.
#define BB 16
#define PP 12
#define NN 2048
#define HH 64
#define NH (NN*HH)          // 131072
#define BPc (BB*PP)         // 192
#define EE 16384
#define EPSV 1e-5f
#define BSTRIDE (NN*PP*HH*2)   // 3,145,728 bytes: one batch slice of g_xgh

// -------- scratch in __device__ globals (no allocations allowed) ----------
// g_xgh layout: [b][n][p][h] (fp16 x*gw) -> per-node row of 1536B contiguous
__device__ __half2 g_xgh[BB*NN*PP*HH/2];   // 50 MB
// g_yh layout: [b][p][n][h] (fp16 y)
__device__ __half2 g_yh [BB*PP*NN*HH/2];   // 50 MB
__device__ float2  g_part1[BPc*4];
__device__ float2  g_part2[BPc*256];
__device__ float2  g_stats2[BPc];
__device__ int     g_rowptr[NN+1];
__device__ uint2   g_sn[EE];            // per sorted slot: (src*64, norm bits)
__device__ uint2   g_AB[NN*32];         // packed half2 A | half2 B per (node, h-pair)

// ---------------- CSR build: ONE single-block kernel, smem-resident -------
#define SMEM_CSR (EE*4*3 + NN*4 + (NN+1)*4 + NN*4 + 128)
__global__ void k_csr(const void* __restrict__ ei) {
    extern __shared__ char sraw[];
    int*   sdst  = (int*)sraw;
    int*   ssrc  = sdst + EE;
    int*   sbuck = ssrc + EE;
    int*   sdeg  = sbuck + EE;        // doubles as scatter cursor later
    int*   srp   = sdeg + NN;
    float* sdinv = (float*)(srp + NN + 1);
    int*   swarp = (int*)(sdinv + NN);
    __shared__ int s_is64;
    int t = threadIdx.x, lane = t & 31, wid = t >> 5;

    // edge dtype detection (jax may emit int32 despite jnp.int64)
    if (t < 32) {
        long long v = ((const long long*)ei)[t];
        int ok = (v >= 0 && v < (long long)NN);
        unsigned m = __ballot_sync(0xffffffffu, ok);
        if (t == 0) s_is64 = (m == 0xffffffffu) ? 1 : 0;
    }
    for (int i = t; i < NN; i += 1024) sdeg[i] = 0;
    __syncthreads();
    int is64 = s_is64;

    for (int e = t; e < EE; e += 1024) {
        int s, d;
        if (is64) {
            s = (int)((const long long*)ei)[e];
            d = (int)((const long long*)ei)[EE + e];
        } else {
            s = ((const int*)ei)[e];
            d = ((const int*)ei)[EE + e];
        }
        ssrc[e] = s; sdst[e] = d;
        atomicAdd(&sdeg[d], 1);
    }
    __syncthreads();

    // exclusive scan of deg[2048] via warp shuffles
    int a  = sdeg[2*t], b2 = sdeg[2*t+1];
    int v  = a + b2;
    #pragma unroll
    for (int off = 1; off < 32; off <<= 1) {
        int u = __shfl_up_sync(0xffffffffu, v, off);
        if (lane >= off) v += u;
    }
    if (lane == 31) swarp[wid] = v;
    __syncthreads();
    if (wid == 0) {
        int u = swarp[lane];
        #pragma unroll
        for (int off = 1; off < 32; off <<= 1) {
            int x2 = __shfl_up_sync(0xffffffffu, u, off);
            if (lane >= off) u += x2;
        }
        swarp[lane] = u;
    }
    __syncthreads();
    int woff = wid ? swarp[wid-1] : 0;
    int incl = v + woff;
    int excl = incl - (a + b2);
    srp[2*t]   = excl;        g_rowptr[2*t]   = excl;
    srp[2*t+1] = excl + a;    g_rowptr[2*t+1] = excl + a;
    if (t == 1023) { srp[NN] = incl; g_rowptr[NN] = incl; }
    sdinv[2*t]   = a  ? rsqrtf((float)a)  : 0.f;
    sdinv[2*t+1] = b2 ? rsqrtf((float)b2) : 0.f;
    sdeg[2*t] = 0; sdeg[2*t+1] = 0;
    __syncthreads();

    for (int e = t; e < EE; e += 1024) {
        int d = sdst[e];
        int pos = srp[d] + atomicAdd(&sdeg[d], 1);
        sbuck[pos] = e;
    }
    __syncthreads();

    // sort each bucket by edge id (deterministic accumulation), fill (src*64, norm)
    for (int n = t; n < NN; n += 1024) {
        int beg = srp[n], end = srp[n+1];
        for (int i = beg + 1; i < end; i++) {
            int key = sbuck[i]; int j = i - 1;
            while (j >= beg && sbuck[j] > key) { sbuck[j+1] = sbuck[j]; j--; }
            sbuck[j+1] = key;
        }
        float dn = sdinv[n];
        for (int i = beg; i < end; i++) {
            int s = ssrc[sbuck[i]];
            g_sn[i] = make_uint2((unsigned)(s * HH),
                                 __float_as_uint(sdinv[s] * dn));
        }
    }
}

// ---- A[dst,h]=Σnrm*gw[src,h], B[dst,h]=Σnrm*gb[src,h] (bp-independent) ---
__global__ void k_ab(const float* __restrict__ gw, const float* __restrict__ gb) {
    int w = threadIdx.x >> 5, l = threadIdx.x & 31;
    int n = blockIdx.x * 8 + w;
    int beg = g_rowptr[n], end = g_rowptr[n+1];
    float A0 = 0.f, A1 = 0.f, B0 = 0.f, B1 = 0.f;
    for (int i = beg; i < end; i++) {
        uint2 sn = g_sn[i];                 // sn.x = src*64 (float offset)
        float nrm = __uint_as_float(sn.y);
        float2 w2 = *(const float2*)(gw + sn.x + 2*l);
        float2 b2 = *(const float2*)(gb + sn.x + 2*l);
        A0 = fmaf(nrm, w2.x, A0); A1 = fmaf(nrm, w2.y, A1);
        B0 = fmaf(nrm, b2.x, B0); B1 = fmaf(nrm, b2.y, B1);
    }
    __half2 hA = __floats2half2_rn(A0, A1);
    __half2 hB = __floats2half2_rn(B0, B1);
    g_AB[n*32 + l] = make_uint2(*reinterpret_cast<unsigned*>(&hA),
                                *reinterpret_cast<unsigned*>(&hB));
}

// -------- LN1 stats + fp16(x*gw) write in [b][n][p][h] layout -------------
// 2 float4 per iteration -> 4 independent LDG.128 + one STG.128 per iter.
__global__ void k_stats1(const float4* __restrict__ x4,
                         const float4* __restrict__ gw4) {
    int bp = blockIdx.y, ch = blockIdx.x, t = threadIdx.x;
    int b = bp / PP, p = bp - b*PP;
    float s = 0.f, q = 0.f;
    uint4* xg4 = (uint4*)g_xgh;
    #pragma unroll
    for (int i = 0; i < 16; i++) {
        int loc = ch*8192 + i*512 + 2*t;          // even float4 index in slice
        float4 v0 = x4[bp*(NH/4) + loc];
        float4 v1 = x4[bp*(NH/4) + loc + 1];
        float4 g0 = gw4[loc];
        float4 g1 = gw4[loc + 1];
        s += v0.x + v0.y + v0.z + v0.w + v1.x + v1.y + v1.z + v1.w;
        q += v0.x*v0.x + v0.y*v0.y + v0.z*v0.z + v0.w*v0.w
           + v1.x*v1.x + v1.y*v1.y + v1.z*v1.z + v1.w*v1.w;
        __half2 h0 = __floats2half2_rn(v0.x*g0.x, v0.y*g0.y);
        __half2 h1 = __floats2half2_rn(v0.z*g0.z, v0.w*g0.w);
        __half2 h2 = __floats2half2_rn(v1.x*g1.x, v1.y*g1.y);
        __half2 h3 = __floats2half2_rn(v1.z*g1.z, v1.w*g1.w);
        int n  = loc >> 4;                        // node (loc, loc+1 same n)
        int h8 = (loc & 15) >> 1;                 // 8-half group within row
        xg4[((b*NN + n)*PP + p)*8 + h8] =
            make_uint4(*reinterpret_cast<unsigned*>(&h0),
                       *reinterpret_cast<unsigned*>(&h1),
                       *reinterpret_cast<unsigned*>(&h2),
                       *reinterpret_cast<unsigned*>(&h3));
    }
    __shared__ float ss[256], sq[256];
    ss[t] = s; sq[t] = q; __syncthreads();
    for (int off = 128; off > 0; off >>= 1) {
        if (t < off) { ss[t] += ss[t+off]; sq[t] += sq[t+off]; }
        __syncthreads();
    }
    if (t == 0) g_part1[bp*4 + ch] = make_float2(ss[0], sq[0]);
}

// -- fused gather: warp = (node, p-group of 4, batch-QUAD) -----------------
__device__ __forceinline__ void upd(unsigned u, float nrm, float2& a) {
    float2 f = __half22float2(*reinterpret_cast<__half2*>(&u));
    a.x = fmaf(nrm, f.x, a.x);
    a.y = fmaf(nrm, f.y, a.y);
}
__device__ __forceinline__ void upd4(const uint4& c, float nrm, float2* a) {
    upd(c.x, nrm, a[0]); upd(c.y, nrm, a[1]);
    upd(c.z, nrm, a[2]); upd(c.w, nrm, a[3]);
}
__device__ __forceinline__ void loadrow(const char* base, unsigned off, uint4* dst) {
    const char* p = base + off * 24u;
    dst[0] = *(const uint4*)p;
    dst[1] = *(const uint4*)(p + BSTRIDE);
    dst[2] = *(const uint4*)(p + 2*BSTRIDE);
    dst[3] = *(const uint4*)(p + 3*(size_t)BSTRIDE);
}

__global__ void __launch_bounds__(256, 3) k_conv() {
    __shared__ float2 sstats[4][PP];
    __shared__ float  ssum[4][4][8], ssq[4][4][8];   // [bsel][pg][warp]
    int bq = blockIdx.z;                             // batch quad: b = 4bq..4bq+3
    int g  = blockIdx.y;                             // p-group: p = 4g..4g+3
    int t  = threadIdx.x;
    if (t < 4*PP) {                                  // inline LN1 finalize (4 b)
        int bsel = t / PP, p = t - bsel*PP;
        int bp = (4*bq + bsel)*PP + p;
        float s = 0.f, q = 0.f;
        for (int i = 0; i < 4; i++) { float2 v = g_part1[bp*4+i]; s += v.x; q += v.y; }
        float mean = s / (float)NH;
        float var  = q / (float)NH - mean*mean;
        sstats[bsel][p] = make_float2(mean, rsqrtf(var + EPSV));
    }
    __syncthreads();

    int w = t >> 5, l = t & 31;
    int n = blockIdx.x * 8 + w;
    int beg = g_rowptr[n], end = g_rowptr[n+1];
    // lane base for b0; b1..b3 = +BSTRIDE..+3*BSTRIDE (mostly LDG imm offsets)
    const char* base = (const char*)g_xgh
                     + (size_t)(4*bq) * BSTRIDE + (g*32 + l) * 16;

    float2 acc[4][4];                                 // [bsel][m]
    #pragma unroll
    for (int bs = 0; bs < 4; bs++)
        #pragma unroll
        for (int m = 0; m < 4; m++) acc[bs][m] = make_float2(0.f, 0.f);

    int len = end - beg;
    const uint2* sp = g_sn + beg;
    uint2 iA, iB;
    uint4 vA[4], vB[4];
    if (len > 0) { iA = sp[0]; loadrow(base, iA.x, vA); }
    if (len > 1) { iB = sp[1]; loadrow(base, iB.x, vB); }
    int j = 0;
    for (; j + 2 < len; j += 2) {
        float nA = __uint_as_float(iA.y);
        #pragma unroll
        for (int bs = 0; bs < 4; bs++) upd4(vA[bs], nA, acc[bs]);
        iA = sp[j+2];                                  // slot A refills itself
        loadrow(base, iA.x, vA);
        float nB = __uint_as_float(iB.y);
        #pragma unroll
        for (int bs = 0; bs < 4; bs++) upd4(vB[bs], nB, acc[bs]);
        if (j + 3 < len) {                             // slot B refills itself
            iB = sp[j+3];
            loadrow(base, iB.x, vB);
        }
    }
    if (j < len) {
        float nA = __uint_as_float(iA.y);
        #pragma unroll
        for (int bs = 0; bs < 4; bs++) upd4(vA[bs], nA, acc[bs]);
    }
    if (j + 1 < len) {
        float nB = __uint_as_float(iB.y);
        #pragma unroll
        for (int bs = 0; bs < 4; bs++) upd4(vB[bs], nB, acc[bs]);
    }

    // lane l owns p = 4g + (l>>3), h = 8*(l&7)..+7
    int g8 = l & 7, pg = l >> 3;
    int p  = 4*g + pg;
    uint2 ab[4];
    #pragma unroll
    for (int m = 0; m < 4; m++) ab[m] = g_AB[n*32 + 4*g8 + m];

    #pragma unroll
    for (int bsel = 0; bsel < 4; bsel++) {
        float2 st = sstats[bsel][p];
        float r = st.y, mr = st.x * st.y;
        unsigned hy[4];
        float s1 = 0.f, q1 = 0.f;
        #pragma unroll
        for (int m = 0; m < 4; m++) {
            float2 A  = __half22float2(*reinterpret_cast<__half2*>(&ab[m].x));
            float2 Bv = __half22float2(*reinterpret_cast<__half2*>(&ab[m].y));
            float y0 = fmaf(r, acc[bsel][m].x, fmaf(-mr, A.x, Bv.x));
            float y1 = fmaf(r, acc[bsel][m].y, fmaf(-mr, A.y, Bv.y));
            __half2 h = __floats2half2_rn(y0, y1);
            hy[m] = *reinterpret_cast<unsigned*>(&h);
            s1 += y0 + y1;
            q1 += y0*y0 + y1*y1;
        }
        ((uint4*)g_yh)[(size_t)((4*bq + bsel)*PP + p)*(NH/8) + n*8 + g8] =
            make_uint4(hy[0], hy[1], hy[2], hy[3]);
        // deterministic butterfly over the 8 lanes sharing this p
        #pragma unroll
        for (int off = 1; off < 8; off <<= 1) {
            s1 += __shfl_xor_sync(0xffffffffu, s1, off);
            q1 += __shfl_xor_sync(0xffffffffu, q1, off);
        }
        if (g8 == 0) { ssum[bsel][pg][w] = s1; ssq[bsel][pg][w] = q1; }
    }
    __syncthreads();
    if (t < 16) {
        int bsel = t >> 2, pq = t & 3;
        float s = 0.f, q = 0.f;
        for (int i = 0; i < 8; i++) { s += ssum[bsel][pq][i]; q += ssq[bsel][pq][i]; }
        g_part2[((4*bq + bsel)*PP + 4*g + pq)*256 + blockIdx.x] = make_float2(s, q);
    }
}

__global__ void k_stats2() {
    int bp = blockIdx.x, t = threadIdx.x;
    float2 v = g_part2[bp*256 + t];
    __shared__ float ss[256], sq[256];
    ss[t] = v.x; sq[t] = v.y; __syncthreads();
    for (int off = 128; off > 0; off >>= 1) {
        if (t < off) { ss[t] += ss[t+off]; sq[t] += sq[t+off]; }
        __syncthreads();
    }
    if (t == 0) {
        float mean = ss[0] / (float)NH;
        float var  = sq[0] / (float)NH - mean*mean;
        g_stats2[bp] = make_float2(mean, rsqrtf(var + EPSV));
    }
}

// -------- fused LN2 + 1x1 conv over periods + bias (float4 vectorized) ----
__global__ void k_out(const float4* __restrict__ tw4,
                      const float4* __restrict__ tb4,
                      const float*  __restrict__ cw,
                      const float*  __restrict__ cb,
                      float4* __restrict__ out4) {
    __shared__ float  scw[144], srow[12], scb[12];
    __shared__ float2 sst[12];
    int t   = threadIdx.x;
    int gid = blockIdx.x * 256 + t;         // 524288 total (16 b * 2048 n * 16 h4)
    int b   = gid >> 15;                    // 32768 positions per batch
    if (t < 144)             scw[t]       = cw[t];
    if (t >= 144 && t < 156) scb[t-144]   = cb[t-144];
    if (t >= 160 && t < 172) sst[t-160]   = g_stats2[b*PP + (t-160)];
    __syncthreads();
    if (t < 12) {
        float s = 0.f;
        for (int p = 0; p < 12; p++) s += scw[t*12 + p];
        srow[t] = s;
    }
    __syncthreads();

    int h4   = gid & 15;
    int n    = (gid >> 4) & 2047;
    int pos4 = n*16 + h4;

    const uint2* y4 = (const uint2*)g_yh;
    float4 tv[12];
    #pragma unroll
    for (int p = 0; p < 12; p++) {
        uint2 u = y4[(b*PP + p)*(NH/4) + pos4];
        float2 f0 = __half22float2(*reinterpret_cast<__half2*>(&u.x));
        float2 f1 = __half22float2(*reinterpret_cast<__half2*>(&u.y));
        float2 st = sst[p];
        tv[p].x = (f0.x - st.x) * st.y;
        tv[p].y = (f0.y - st.x) * st.y;
        tv[p].z = (f1.x - st.x) * st.y;
        tv[p].w = (f1.y - st.x) * st.y;
    }
    float4 tw = tw4[pos4];
    float4 tb = tb4[pos4];

    #pragma unroll
    for (int q = 0; q < 12; q++) {
        float ax = 0.f, ay = 0.f, az = 0.f, aw = 0.f;
        #pragma unroll
        for (int p = 0; p < 12; p++) {
            float c = scw[q*12 + p];
            ax = fmaf(c, tv[p].x, ax);
            ay = fmaf(c, tv[p].y, ay);
            az = fmaf(c, tv[p].z, az);
            aw = fmaf(c, tv[p].w, aw);
        }
        float4 o;
        o.x = fmaf(tw.x, ax, fmaf(tb.x, srow[q], scb[q]));
        o.y = fmaf(tw.y, ay, fmaf(tb.y, srow[q], scb[q]));
        o.z = fmaf(tw.z, az, fmaf(tb.z, srow[q], scb[q]));
        o.w = fmaf(tw.w, aw, fmaf(tb.w, srow[q], scb[q]));
        out4[(b*PP + q)*(NH/4) + pos4] = o;
    }
}

// ---- one-time host objects (created at load, before harness checkpoints) --
struct _CondBlockInit {
    cudaStream_t sB;
    cudaEvent_t  evFork, evJoin;
    _CondBlockInit() {
        cudaStreamCreateWithFlags(&sB, cudaStreamNonBlocking);
        cudaEventCreateWithFlags(&evFork, cudaEventDisableTiming);
        cudaEventCreateWithFlags(&evJoin, cudaEventDisableTiming);
        cudaFuncSetAttribute(k_csr, cudaFuncAttributeMaxDynamicSharedMemorySize,
                             SMEM_CSR);
    }
};
static _CondBlockInit g_ini;

// --------------------------------------------------------------------------
extern "C" void kernel_launch(void* const* d_in, const int* in_sizes, int n_in,
                              void* d_out, int out_size) {
    const float* x  = (const float*)d_in[0];
    const void*  ei = d_in[1];
    const float* gw = (const float*)d_in[2];
    const float* gb = (const float*)d_in[3];
    const float* tw = (const float*)d_in[4];
    const float* tb = (const float*)d_in[5];
    const float* cw = (const float*)d_in[6];
    const float* cb = (const float*)d_in[7];
    float4* out = (float4*)d_out;

    // fork: side stream runs CSR build + AB precompute (k_csr uses ONE SM,
    // so overlapping it with the full-chip stats1 is a real win); join
    // before k_conv. Full-chip kernels stay strictly serial — overlapping
    // SM-saturating kernels is zero-sum (R14/R15 evidence).
    cudaEventRecord(g_ini.evFork, 0);
    cudaStreamWaitEvent(g_ini.sB, g_ini.evFork, 0);
    k_csr <<<1, 1024, SMEM_CSR, g_ini.sB>>>(ei);
    k_ab  <<<256, 256, 0, g_ini.sB>>>(gw, gb);
    cudaEventRecord(g_ini.evJoin, g_ini.sB);

    k_stats1 <<<dim3(4, BPc), 256>>>((const float4*)x, (const float4*)gw);

    cudaStreamWaitEvent(0, g_ini.evJoin, 0);
    k_conv   <<<dim3(NN/8, 3, BB/4), 256>>>();
    k_stats2 <<<BPc, 256>>>();
    k_out    <<<2048, 256>>>((const float4*)tw, (const float4*)tb, cw, cb, out);
}

// round 17
// speedup vs baseline: 1.1564x; 1.1139x over previous
#include <cuda_runtime.h>
#include <cuda_fp16.h>

// Shapes fixed by the problem: B=16, P=12, N=2048, H=64, E=16384, Q=P.
#define BB 16
#define PP 12
#define NN 2048
#define HH 64
#define NH (NN*HH)          // 131072
#define BPc (BB*PP)         // 192
#define EE 16384
#define EPSV 1e-5f
#define BSTRIDE (NN*PP*HH*2)   // 3,145,728 bytes: one batch slice of g_xgh

typedef unsigned long long u64;
#define FMA2(d,a,b,c) asm("fma.rn.f32x2 %0, %1, %2, %3;" : "=l"(d) : "l"(a), "l"(b), "l"(c))
#define PACK2(d,lo,hi) asm("mov.b64 %0, {%1, %2};" : "=l"(d) : "f"(lo), "f"(hi))
#define UNPK2(lo,hi,s) asm("mov.b64 {%0, %1}, %2;" : "=f"(lo), "=f"(hi) : "l"(s))

// -------- scratch in __device__ globals (no allocations allowed) ----------
// g_xgh layout: [b][n][p][h] (fp16 x*gw) -> per-node row of 1536B contiguous
__device__ __half2 g_xgh[BB*NN*PP*HH/2];   // 50 MB
// g_yh layout: [b][p][n][h] (fp16 y)
__device__ __half2 g_yh [BB*PP*NN*HH/2];   // 50 MB
__device__ float2  g_part1[BPc*4];
__device__ float2  g_part2[BPc*256];
__device__ float2  g_stats2[BPc];
__device__ int     g_rowptr[NN+1];
__device__ uint2   g_sn[EE];            // per sorted slot: (src*64, norm bits)
__device__ uint2   g_AB[NN*32];         // packed half2 A | half2 B per (node, h-pair)

// ---------------- CSR build: ONE single-block kernel, smem-resident -------
#define SMEM_CSR (EE*4*3 + NN*4 + (NN+1)*4 + NN*4 + 128)
__global__ void k_csr(const void* __restrict__ ei) {
    extern __shared__ char sraw[];
    int*   sdst  = (int*)sraw;
    int*   ssrc  = sdst + EE;
    int*   sbuck = ssrc + EE;
    int*   sdeg  = sbuck + EE;        // doubles as scatter cursor later
    int*   srp   = sdeg + NN;
    float* sdinv = (float*)(srp + NN + 1);
    int*   swarp = (int*)(sdinv + NN);
    __shared__ int s_is64;
    int t = threadIdx.x, lane = t & 31, wid = t >> 5;

    // edge dtype detection (jax may emit int32 despite jnp.int64)
    if (t < 32) {
        long long v = ((const long long*)ei)[t];
        int ok = (v >= 0 && v < (long long)NN);
        unsigned m = __ballot_sync(0xffffffffu, ok);
        if (t == 0) s_is64 = (m == 0xffffffffu) ? 1 : 0;
    }
    for (int i = t; i < NN; i += 1024) sdeg[i] = 0;
    __syncthreads();
    int is64 = s_is64;

    for (int e = t; e < EE; e += 1024) {
        int s, d;
        if (is64) {
            s = (int)((const long long*)ei)[e];
            d = (int)((const long long*)ei)[EE + e];
        } else {
            s = ((const int*)ei)[e];
            d = ((const int*)ei)[EE + e];
        }
        ssrc[e] = s; sdst[e] = d;
        atomicAdd(&sdeg[d], 1);
    }
    __syncthreads();

    // exclusive scan of deg[2048] via warp shuffles
    int a  = sdeg[2*t], b2 = sdeg[2*t+1];
    int v  = a + b2;
    #pragma unroll
    for (int off = 1; off < 32; off <<= 1) {
        int u = __shfl_up_sync(0xffffffffu, v, off);
        if (lane >= off) v += u;
    }
    if (lane == 31) swarp[wid] = v;
    __syncthreads();
    if (wid == 0) {
        int u = swarp[lane];
        #pragma unroll
        for (int off = 1; off < 32; off <<= 1) {
            int x2 = __shfl_up_sync(0xffffffffu, u, off);
            if (lane >= off) u += x2;
        }
        swarp[lane] = u;
    }
    __syncthreads();
    int woff = wid ? swarp[wid-1] : 0;
    int incl = v + woff;
    int excl = incl - (a + b2);
    srp[2*t]   = excl;        g_rowptr[2*t]   = excl;
    srp[2*t+1] = excl + a;    g_rowptr[2*t+1] = excl + a;
    if (t == 1023) { srp[NN] = incl; g_rowptr[NN] = incl; }
    sdinv[2*t]   = a  ? rsqrtf((float)a)  : 0.f;
    sdinv[2*t+1] = b2 ? rsqrtf((float)b2) : 0.f;
    sdeg[2*t] = 0; sdeg[2*t+1] = 0;
    __syncthreads();

    for (int e = t; e < EE; e += 1024) {
        int d = sdst[e];
        int pos = srp[d] + atomicAdd(&sdeg[d], 1);
        sbuck[pos] = e;
    }
    __syncthreads();

    // sort each bucket by edge id (deterministic accumulation), fill (src*64, norm)
    for (int n = t; n < NN; n += 1024) {
        int beg = srp[n], end = srp[n+1];
        for (int i = beg + 1; i < end; i++) {
            int key = sbuck[i]; int j = i - 1;
            while (j >= beg && sbuck[j] > key) { sbuck[j+1] = sbuck[j]; j--; }
            sbuck[j+1] = key;
        }
        float dn = sdinv[n];
        for (int i = beg; i < end; i++) {
            int s = ssrc[sbuck[i]];
            g_sn[i] = make_uint2((unsigned)(s * HH),
                                 __float_as_uint(sdinv[s] * dn));
        }
    }
}

// ---- A[dst,h]=Σnrm*gw[src,h], B[dst,h]=Σnrm*gb[src,h] (bp-independent) ---
__global__ void k_ab(const float* __restrict__ gw, const float* __restrict__ gb) {
    int w = threadIdx.x >> 5, l = threadIdx.x & 31;
    int n = blockIdx.x * 8 + w;
    int beg = g_rowptr[n], end = g_rowptr[n+1];
    float A0 = 0.f, A1 = 0.f, B0 = 0.f, B1 = 0.f;
    for (int i = beg; i < end; i++) {
        uint2 sn = g_sn[i];                 // sn.x = src*64 (float offset)
        float nrm = __uint_as_float(sn.y);
        float2 w2 = *(const float2*)(gw + sn.x + 2*l);
        float2 b2 = *(const float2*)(gb + sn.x + 2*l);
        A0 = fmaf(nrm, w2.x, A0); A1 = fmaf(nrm, w2.y, A1);
        B0 = fmaf(nrm, b2.x, B0); B1 = fmaf(nrm, b2.y, B1);
    }
    __half2 hA = __floats2half2_rn(A0, A1);
    __half2 hB = __floats2half2_rn(B0, B1);
    g_AB[n*32 + l] = make_uint2(*reinterpret_cast<unsigned*>(&hA),
                                *reinterpret_cast<unsigned*>(&hB));
}

// -------- LN1 stats + fp16(x*gw) write in [b][n][p][h] layout -------------
// (exact R13 version — the R15 "ILP" restructure regressed and is reverted)
__global__ void k_stats1(const float4* __restrict__ x4,
                         const float4* __restrict__ gw4) {
    int bp = blockIdx.y, ch = blockIdx.x, t = threadIdx.x;
    int b = bp / PP, p = bp - b*PP;
    float s = 0.f, q = 0.f;
    uint2* xg2 = (uint2*)g_xgh;
    #pragma unroll
    for (int i = 0; i < 32; i++) {
        int loc = ch*8192 + i*256 + t;            // float4 index within slice
        float4 v = x4[bp*(NH/4) + loc];
        s += v.x + v.y + v.z + v.w;
        q += v.x*v.x + v.y*v.y + v.z*v.z + v.w*v.w;
        float4 g = gw4[loc];
        __half2 h0 = __floats2half2_rn(v.x*g.x, v.y*g.y);
        __half2 h1 = __floats2half2_rn(v.z*g.z, v.w*g.w);
        int n  = loc >> 4;                        // node
        int h4 = loc & 15;                        // 4-half group within row
        xg2[((b*NN + n)*PP + p)*16 + h4] =
            make_uint2(*reinterpret_cast<unsigned*>(&h0),
                       *reinterpret_cast<unsigned*>(&h1));
    }
    __shared__ float ss[256], sq[256];
    ss[t] = s; sq[t] = q; __syncthreads();
    for (int off = 128; off > 0; off >>= 1) {
        if (t < off) { ss[t] += ss[t+off]; sq[t] += sq[t+off]; }
        __syncthreads();
    }
    if (t == 0) g_part1[bp*4 + ch] = make_float2(ss[0], sq[0]);
}

// -- fused gather: warp = (node, p-group of 4, batch-QUAD) -----------------
__device__ __forceinline__ void upd(unsigned u, float nrm, float2& a) {
    float2 f = __half22float2(*reinterpret_cast<__half2*>(&u));
    a.x = fmaf(nrm, f.x, a.x);
    a.y = fmaf(nrm, f.y, a.y);
}
__device__ __forceinline__ void upd4(const uint4& c, float nrm, float2* a) {
    upd(c.x, nrm, a[0]); upd(c.y, nrm, a[1]);
    upd(c.z, nrm, a[2]); upd(c.w, nrm, a[3]);
}
__device__ __forceinline__ void loadrow(const char* base, unsigned off, uint4* dst) {
    const char* p = base + off * 24u;
    dst[0] = *(const uint4*)p;
    dst[1] = *(const uint4*)(p + BSTRIDE);
    dst[2] = *(const uint4*)(p + 2*BSTRIDE);
    dst[3] = *(const uint4*)(p + 3*(size_t)BSTRIDE);
}

__global__ void __launch_bounds__(256, 3) k_conv() {
    __shared__ float2 sstats[4][PP];
    __shared__ float  ssum[4][4][8], ssq[4][4][8];   // [bsel][pg][warp]
    int bq = blockIdx.z;                             // batch quad: b = 4bq..4bq+3
    int g  = blockIdx.y;                             // p-group: p = 4g..4g+3
    int t  = threadIdx.x;
    if (t < 4*PP) {                                  // inline LN1 finalize (4 b)
        int bsel = t / PP, p = t - bsel*PP;
        int bp = (4*bq + bsel)*PP + p;
        float s = 0.f, q = 0.f;
        for (int i = 0; i < 4; i++) { float2 v = g_part1[bp*4+i]; s += v.x; q += v.y; }
        float mean = s / (float)NH;
        float var  = q / (float)NH - mean*mean;
        sstats[bsel][p] = make_float2(mean, rsqrtf(var + EPSV));
    }
    __syncthreads();

    int w = t >> 5, l = t & 31;
    int n = blockIdx.x * 8 + w;
    int beg = g_rowptr[n], end = g_rowptr[n+1];
    // lane base for b0; b1..b3 = +BSTRIDE..+3*BSTRIDE (mostly LDG imm offsets)
    const char* base = (const char*)g_xgh
                     + (size_t)(4*bq) * BSTRIDE + (g*32 + l) * 16;

    float2 acc[4][4];                                 // [bsel][m]
    #pragma unroll
    for (int bs = 0; bs < 4; bs++)
        #pragma unroll
        for (int m = 0; m < 4; m++) acc[bs][m] = make_float2(0.f, 0.f);

    int len = end - beg;
    const uint2* sp = g_sn + beg;
    uint2 iA, iB;
    uint4 vA[4], vB[4];
    if (len > 0) { iA = sp[0]; loadrow(base, iA.x, vA); }
    if (len > 1) { iB = sp[1]; loadrow(base, iB.x, vB); }
    int j = 0;
    for (; j + 2 < len; j += 2) {
        float nA = __uint_as_float(iA.y);
        #pragma unroll
        for (int bs = 0; bs < 4; bs++) upd4(vA[bs], nA, acc[bs]);
        iA = sp[j+2];                                  // slot A refills itself
        loadrow(base, iA.x, vA);
        float nB = __uint_as_float(iB.y);
        #pragma unroll
        for (int bs = 0; bs < 4; bs++) upd4(vB[bs], nB, acc[bs]);
        if (j + 3 < len) {                             // slot B refills itself
            iB = sp[j+3];
            loadrow(base, iB.x, vB);
        }
    }
    if (j < len) {
        float nA = __uint_as_float(iA.y);
        #pragma unroll
        for (int bs = 0; bs < 4; bs++) upd4(vA[bs], nA, acc[bs]);
    }
    if (j + 1 < len) {
        float nB = __uint_as_float(iB.y);
        #pragma unroll
        for (int bs = 0; bs < 4; bs++) upd4(vB[bs], nB, acc[bs]);
    }

    // lane l owns p = 4g + (l>>3), h = 8*(l&7)..+7
    int g8 = l & 7, pg = l >> 3;
    int p  = 4*g + pg;
    uint2 ab[4];
    #pragma unroll
    for (int m = 0; m < 4; m++) ab[m] = g_AB[n*32 + 4*g8 + m];

    #pragma unroll
    for (int bsel = 0; bsel < 4; bsel++) {
        float2 st = sstats[bsel][p];
        float r = st.y, mr = st.x * st.y;
        unsigned hy[4];
        float s1 = 0.f, q1 = 0.f;
        #pragma unroll
        for (int m = 0; m < 4; m++) {
            float2 A  = __half22float2(*reinterpret_cast<__half2*>(&ab[m].x));
            float2 Bv = __half22float2(*reinterpret_cast<__half2*>(&ab[m].y));
            float y0 = fmaf(r, acc[bsel][m].x, fmaf(-mr, A.x, Bv.x));
            float y1 = fmaf(r, acc[bsel][m].y, fmaf(-mr, A.y, Bv.y));
            __half2 h = __floats2half2_rn(y0, y1);
            hy[m] = *reinterpret_cast<unsigned*>(&h);
            s1 += y0 + y1;
            q1 += y0*y0 + y1*y1;
        }
        ((uint4*)g_yh)[(size_t)((4*bq + bsel)*PP + p)*(NH/8) + n*8 + g8] =
            make_uint4(hy[0], hy[1], hy[2], hy[3]);
        // deterministic butterfly over the 8 lanes sharing this p
        #pragma unroll
        for (int off = 1; off < 8; off <<= 1) {
            s1 += __shfl_xor_sync(0xffffffffu, s1, off);
            q1 += __shfl_xor_sync(0xffffffffu, q1, off);
        }
        if (g8 == 0) { ssum[bsel][pg][w] = s1; ssq[bsel][pg][w] = q1; }
    }
    __syncthreads();
    if (t < 16) {
        int bsel = t >> 2, pq = t & 3;
        float s = 0.f, q = 0.f;
        for (int i = 0; i < 8; i++) { s += ssum[bsel][pq][i]; q += ssq[bsel][pq][i]; }
        g_part2[((4*bq + bsel)*PP + 4*g + pq)*256 + blockIdx.x] = make_float2(s, q);
    }
}

__global__ void k_stats2() {
    int bp = blockIdx.x, t = threadIdx.x;
    float2 v = g_part2[bp*256 + t];
    __shared__ float ss[256], sq[256];
    ss[t] = v.x; sq[t] = v.y; __syncthreads();
    for (int off = 128; off > 0; off >>= 1) {
        if (t < off) { ss[t] += ss[t+off]; sq[t] += sq[t+off]; }
        __syncthreads();
    }
    if (t == 0) {
        float mean = ss[0] / (float)NH;
        float var  = sq[0] / (float)NH - mean*mean;
        g_stats2[bp] = make_float2(mean, rsqrtf(var + EPSV));
    }
}

// -------- fused LN2 + 1x1 conv over periods + bias — packed f32x2 math ----
__global__ void k_out(const float4* __restrict__ tw4,
                      const float4* __restrict__ tb4,
                      const float*  __restrict__ cw,
                      const float*  __restrict__ cb,
                      float4* __restrict__ out4) {
    __shared__ float  scw[144];
    __shared__ u64    scw2[144], scb2[12], ssrow2[12];
    __shared__ float2 sst[12];
    int t   = threadIdx.x;
    int gid = blockIdx.x * 256 + t;         // 524288 total (16 b * 2048 n * 16 h4)
    int b   = gid >> 15;                    // 32768 positions per batch
    if (t < 144) {
        float c = cw[t];
        scw[t] = c;
        PACK2(scw2[t], c, c);
    }
    if (t >= 144 && t < 156) {
        float v = cb[t-144];
        PACK2(scb2[t-144], v, v);
    }
    if (t >= 160 && t < 172) sst[t-160] = g_stats2[b*PP + (t-160)];
    __syncthreads();
    if (t < 12) {
        float s = 0.f;
        for (int p = 0; p < 12; p++) s += scw[t*12 + p];
        PACK2(ssrow2[t], s, s);
    }
    __syncthreads();

    int h4   = gid & 15;
    int n    = (gid >> 4) & 2047;
    int pos4 = n*16 + h4;

    const uint2* y4 = (const uint2*)g_yh;
    u64 tv0[12], tv1[12];                   // packed (x,y) and (z,w) pairs
    #pragma unroll
    for (int p = 0; p < 12; p++) {
        uint2 u = y4[(b*PP + p)*(NH/4) + pos4];
        float2 f0 = __half22float2(*reinterpret_cast<__half2*>(&u.x));
        float2 f1 = __half22float2(*reinterpret_cast<__half2*>(&u.y));
        float2 st = sst[p];
        float r = st.y, nmr = -st.x * st.y;
        u64 rp, cp, a0, a1;
        PACK2(rp, r, r);
        PACK2(cp, nmr, nmr);
        PACK2(a0, f0.x, f0.y);
        PACK2(a1, f1.x, f1.y);
        FMA2(tv0[p], a0, rp, cp);           // (y - m) * r, fused
        FMA2(tv1[p], a1, rp, cp);
    }
    float4 tw = tw4[pos4];
    float4 tb = tb4[pos4];
    u64 tw01, tw23, tb01, tb23;
    PACK2(tw01, tw.x, tw.y); PACK2(tw23, tw.z, tw.w);
    PACK2(tb01, tb.x, tb.y); PACK2(tb23, tb.z, tb.w);

    #pragma unroll
    for (int q = 0; q < 12; q++) {
        u64 a01 = 0ull, a23 = 0ull;         // +0.0f packed twice
        #pragma unroll
        for (int p = 0; p < 12; p++) {
            u64 c2 = scw2[q*12 + p];
            FMA2(a01, c2, tv0[p], a01);
            FMA2(a23, c2, tv1[p], a23);
        }
        u64 o01, o23;
        FMA2(o01, tb01, ssrow2[q], scb2[q]);   // tb*srow + cb
        FMA2(o23, tb23, ssrow2[q], scb2[q]);
        FMA2(o01, tw01, a01, o01);             // tw*acc + base
        FMA2(o23, tw23, a23, o23);
        float4 o;
        UNPK2(o.x, o.y, o01);
        UNPK2(o.z, o.w, o23);
        out4[(b*PP + q)*(NH/4) + pos4] = o;
    }
}

// ---- one-time host objects (created at load, before harness checkpoints) --
struct _CondBlockInit {
    cudaStream_t sB;
    cudaEvent_t  evFork, evJoin;
    _CondBlockInit() {
        cudaStreamCreateWithFlags(&sB, cudaStreamNonBlocking);
        cudaEventCreateWithFlags(&evFork, cudaEventDisableTiming);
        cudaEventCreateWithFlags(&evJoin, cudaEventDisableTiming);
        cudaFuncSetAttribute(k_csr, cudaFuncAttributeMaxDynamicSharedMemorySize,
                             SMEM_CSR);
    }
};
static _CondBlockInit g_ini;

// --------------------------------------------------------------------------
extern "C" void kernel_launch(void* const* d_in, const int* in_sizes, int n_in,
                              void* d_out, int out_size) {
    const float* x  = (const float*)d_in[0];
    const void*  ei = d_in[1];
    const float* gw = (const float*)d_in[2];
    const float* gb = (const float*)d_in[3];
    const float* tw = (const float*)d_in[4];
    const float* tb = (const float*)d_in[5];
    const float* cw = (const float*)d_in[6];
    const float* cb = (const float*)d_in[7];
    float4* out = (float4*)d_out;

    // fork: side stream runs CSR build + AB precompute (k_csr uses ONE SM,
    // so overlapping it with the full-chip stats1 is a real win); join
    // before k_conv. Full-chip kernels stay strictly serial — overlapping
    // SM-saturating kernels is zero-sum (R14/R15 evidence).
    cudaEventRecord(g_ini.evFork, 0);
    cudaStreamWaitEvent(g_ini.sB, g_ini.evFork, 0);
    k_csr <<<1, 1024, SMEM_CSR, g_ini.sB>>>(ei);
    k_ab  <<<256, 256, 0, g_ini.sB>>>(gw, gb);
    cudaEventRecord(g_ini.evJoin, g_ini.sB);

    k_stats1 <<<dim3(4, BPc), 256>>>((const float4*)x, (const float4*)gw);

    cudaStreamWaitEvent(0, g_ini.evJoin, 0);
    k_conv   <<<dim3(NN/8, 3, BB/4), 256>>>();
    k_stats2 <<<BPc, 256>>>();
    k_out    <<<2048, 256>>>((const float4*)tw, (const float4*)tb, cw, cb, out);
}